// round 13
// baseline (speedup 1.0000x reference)
#include <cuda_runtime.h>
#include <cstdint>
#include <math.h>

// ---------------------------------------------------------------------------
// Problem constants
// ---------------------------------------------------------------------------
#define NB      8192
#define ND      64
#define NNEG    128
#define KNBR    32

#define W1c     1e-6f
#define W3c     1e-6f
#define NEG_WEIGHTc 200.0f
#define GAMMAc  1e-4f
#define LAMBDAc 2.5f

#define FULLMASK 0xFFFFFFFFu

// ---------------------------------------------------------------------------
// Scratch (device globals)
// ---------------------------------------------------------------------------
__device__ float g_M[ND * ND];     // M = W_u^T W_i
__device__ float g_cpe[ND];        // W_i^T b_u
__device__ float g_cue[ND];        // W_u^T b_i
__device__ float g_c0;             // b_u . b_i
__device__ float g_norm_partial[NB];
__device__ float g_lossL[NB];
__device__ float g_lossI[NB];
__device__ float g_mseP[NB];
__device__ unsigned g_done;

__device__ __forceinline__ float softplusf(float x) {
    return fmaxf(x, 0.0f) + __logf(1.0f + __expf(-fabsf(x)));
}

__device__ __forceinline__ float bfly(float s) {
    #pragma unroll
    for (int o = 16; o; o >>= 1) s += __shfl_xor_sync(FULLMASK, s, o);
    return s;
}

__device__ __forceinline__ float dot8(float4 va, float4 vb, float4 ua, float4 ub) {
    float s = va.x * ua.x;
    s = fmaf(va.y, ua.y, s);
    s = fmaf(va.z, ua.z, s);
    s = fmaf(va.w, ua.w, s);
    s = fmaf(vb.x, ub.x, s);
    s = fmaf(vb.y, ub.y, s);
    s = fmaf(vb.z, ub.z, s);
    s = fmaf(vb.w, ub.w, s);
    return s;
}

#define BAR_GATHER() asm volatile("bar.sync 1, 128;" ::: "memory")

__device__ __forceinline__ void cp_async16(unsigned dst_smem, const void* src) {
    asm volatile("cp.async.ca.shared.global [%0], [%1], 16;"
                 :: "r"(dst_smem), "l"(src));
}
__device__ __forceinline__ void cp_async_commit() {
    asm volatile("cp.async.commit_group;" ::: "memory");
}
template <int N>
__device__ __forceinline__ void cp_async_wait_n() {
    asm volatile("cp.async.wait_group %0;" :: "n"(N) : "memory");
}

// ---------------------------------------------------------------------------
// Kernel 1: precompute M = W_u^T W_i (+ bias terms), smem-staged.
// Also resets the last-block counter for this graph replay.
// ---------------------------------------------------------------------------
__global__ void __launch_bounds__(256)
precompute_kernel(const float* __restrict__ wu, const float* __restrict__ bu,
                  const float* __restrict__ wi, const float* __restrict__ bi) {
    __shared__ float swu[ND * ND];
    __shared__ float swi[ND * ND];

    const int tid = threadIdx.x;
    if (blockIdx.x == 0 && tid == 0) g_done = 0u;

    {
        const float4* su = (const float4*)wu;
        const float4* si = (const float4*)wi;
        float4* du = (float4*)swu;
        float4* di = (float4*)swi;
        #pragma unroll
        for (int r = 0; r < 4; r++) {
            du[tid + r * 256] = su[tid + r * 256];
            di[tid + r * 256] = si[tid + r * 256];
        }
    }
    __syncthreads();

    const int idx = blockIdx.x * 256 + tid;
    const int a = idx >> 6;
    const int c = idx & 63;
    float a0 = 0.f, a1 = 0.f, a2 = 0.f, a3 = 0.f;
    #pragma unroll
    for (int d = 0; d < ND; d += 4) {
        a0 = fmaf(swu[(d + 0) * ND + a], swi[(d + 0) * ND + c], a0);
        a1 = fmaf(swu[(d + 1) * ND + a], swi[(d + 1) * ND + c], a1);
        a2 = fmaf(swu[(d + 2) * ND + a], swi[(d + 2) * ND + c], a2);
        a3 = fmaf(swu[(d + 3) * ND + a], swi[(d + 3) * ND + c], a3);
    }
    g_M[idx] = (a0 + a1) + (a2 + a3);

    if (blockIdx.x == 0 && tid < ND) {
        const int j = tid;
        float c1 = 0.0f, c2 = 0.0f;
        #pragma unroll 8
        for (int d = 0; d < ND; d++) {
            c1 = fmaf(swi[d * ND + j], bu[d], c1);
            c2 = fmaf(swu[d * ND + j], bi[d], c2);
        }
        g_cpe[j] = c1;
        g_cue[j] = c2;
        if (j == 0) {
            float s = 0.0f;
            #pragma unroll 8
            for (int d = 0; d < ND; d++) s = fmaf(bu[d], bi[d], s);
            g_c0 = s;
        }
    }
}

// ---------------------------------------------------------------------------
// Fused kernel args
// ---------------------------------------------------------------------------
struct FusedArgs {
    const int*   users;
    const int*   pos_items;
    const int*   neg_items;
    const float* rpkms;
    const float* user_emb;  long nu;
    const float* item_emb;  long ni;
    const float* beta_uD;
    const float* beta_iD;
    const int*   ii_nbr;
    const float* ii_con;
    const float* sp[8]; int sn[8];
    float* out;
};

// ---------------------------------------------------------------------------
// norm slice over 128 stream threads: __ldcs, 4 accumulators
// ---------------------------------------------------------------------------
__device__ __forceinline__ float norm_slice_128(const FusedArgs& a) {
    float acc0 = 0.0f, acc1 = 0.0f, acc2 = 0.0f, acc3 = 0.0f;
    const size_t tg = (size_t)blockIdx.x * 128 + threadIdx.x;
    const size_t stride = (size_t)gridDim.x * 128;

    const float4* pu = (const float4*)a.user_emb;
    const size_t mu = (size_t)a.nu >> 2;
    size_t i = tg;
    for (; i + 3 * stride < mu; i += 4 * stride) {
        float4 v0 = __ldcs(pu + i);
        float4 v1 = __ldcs(pu + i + stride);
        float4 v2 = __ldcs(pu + i + 2 * stride);
        float4 v3 = __ldcs(pu + i + 3 * stride);
        acc0 += v0.x*v0.x + v0.y*v0.y + v0.z*v0.z + v0.w*v0.w;
        acc1 += v1.x*v1.x + v1.y*v1.y + v1.z*v1.z + v1.w*v1.w;
        acc2 += v2.x*v2.x + v2.y*v2.y + v2.z*v2.z + v2.w*v2.w;
        acc3 += v3.x*v3.x + v3.y*v3.y + v3.z*v3.z + v3.w*v3.w;
    }
    for (; i < mu; i += stride) {
        float4 v = __ldcs(pu + i);
        acc0 += v.x*v.x + v.y*v.y + v.z*v.z + v.w*v.w;
    }
    const float4* pi = (const float4*)a.item_emb;
    const size_t mi = (size_t)a.ni >> 2;
    i = tg;
    for (; i + 3 * stride < mi; i += 4 * stride) {
        float4 v0 = __ldcs(pi + i);
        float4 v1 = __ldcs(pi + i + stride);
        float4 v2 = __ldcs(pi + i + 2 * stride);
        float4 v3 = __ldcs(pi + i + 3 * stride);
        acc0 += v0.x*v0.x + v0.y*v0.y + v0.z*v0.z + v0.w*v0.w;
        acc1 += v1.x*v1.x + v1.y*v1.y + v1.z*v1.z + v1.w*v1.w;
        acc2 += v2.x*v2.x + v2.y*v2.y + v2.z*v2.z + v2.w*v2.w;
        acc3 += v3.x*v3.x + v3.y*v3.y + v3.z*v3.z + v3.w*v3.w;
    }
    for (; i < mi; i += stride) {
        float4 v = __ldcs(pi + i);
        acc0 += v.x*v.x + v.y*v.y + v.z*v.z + v.w*v.w;
    }
    if (blockIdx.x == 0) {
        #pragma unroll
        for (int j = 0; j < 8; j++) {
            const float* q = a.sp[j];
            const int n = a.sn[j];
            for (int k = threadIdx.x; k < n; k += 128) {
                float v = q[k];
                acc0 += v * v;
            }
        }
    }
    return (acc0 + acc1) + (acc2 + acc3);
}

// ---------------------------------------------------------------------------
// Fused kernel: warp-specialized.
//  warps 0-3 : norm stream
//  warps 4-7 : deep cp.async pipeline (all 10 slots in flight) + dots
//              + matvec + pos + mse
// ---------------------------------------------------------------------------
__global__ void __launch_bounds__(256, 5)
fused_kernel(FusedArgs a) {
    const int b    = blockIdx.x;
    const int tid  = threadIdx.x;
    const int lane = tid & 31;
    const int warp = tid >> 5;

    // per gather warp: flat 10-slot buffer (10 x 1KB = 10KB)
    __shared__ __align__(16) float s_buf[4][10 * 4 * ND];
    __shared__ __align__(16) float s_ue[ND];
    __shared__ __align__(16) float s_pe[ND];
    __shared__ float s_t[ND];
    __shared__ float sN[4], sI[4];
    __shared__ float sPosLoss, sMse;
    __shared__ float sNorm[4];
    __shared__ bool  sLast;

    if (warp < 4) {
        // ================= STREAM WARPS =================
        float nacc = norm_slice_128(a);
        nacc = bfly(nacc);
        if (lane == 0) sNorm[warp] = nacc;
    } else {
        // ================= GATHER WARPS =================
        const int gw    = warp - 4;         // 0..3
        const int wg    = tid - 128;        // 0..127
        const int lane8 = lane & 7;
        const int grp   = lane >> 3;
        const int r16   = lane >> 4;        // 0/1: row pair for staging
        const int sub   = lane & 15;        // 16B chunk within row

        const int u = __ldg(a.users + b);
        const int p = __ldg(a.pos_items + b);

        if (wg < ND)      s_ue[wg]      = __ldg(a.user_emb + (size_t)u * ND + wg);
        else              s_pe[wg - ND] = __ldg(a.item_emb + (size_t)p * ND + (wg - ND));

        // index + scalar prefetch
        const int*   negb = a.neg_items + (size_t)b * NNEG + gw * 32;
        const int*   nbrp = a.ii_nbr   + (size_t)p * KNBR + gw * 8;
        const float* simp = a.ii_con   + (size_t)p * KNBR + gw * 8;
        const int   myneg = __ldg(negb + lane);
        const int   mynbr = (lane < 8) ? __ldg(nbrp + lane) : 0;
        const float mybi  = __ldg(a.beta_iD + myneg);
        const float mysim = (lane < 8) ? __ldg(simp + lane) : 0.0f;
        const float bu    = __ldg(a.beta_uD + u);

        const unsigned buf_base =
            (unsigned)__cvta_generic_to_shared(&s_buf[gw][0]);

        // issue stage for slot k (4 rows, 2 per staging thread), one group each
        auto issue_slot = [&](int k) {
            int j0, j1;
            if (k < 8) {
                j0 = __shfl_sync(FULLMASK, myneg, k * 4 + r16);
                j1 = __shfl_sync(FULLMASK, myneg, k * 4 + r16 + 2);
            } else {
                j0 = __shfl_sync(FULLMASK, mynbr, (k - 8) * 4 + r16);
                j1 = __shfl_sync(FULLMASK, mynbr, (k - 8) * 4 + r16 + 2);
            }
            const unsigned dst = buf_base + (unsigned)(k * 1024)
                               + (unsigned)(r16 * 256 + sub * 16);
            cp_async16(dst,       a.item_emb + (size_t)j0 * ND + sub * 4);
            cp_async16(dst + 512, a.item_emb + (size_t)j1 * ND + sub * 4);
            cp_async_commit();
        };

        // issue ALL 10 slots up front: up to 9 pending groups in flight
        #pragma unroll
        for (int k = 0; k < 10; k++) issue_slot(k);

        BAR_GATHER();   // s_ue / s_pe ready among gather warps

        const float4 ua = ((const float4*)s_ue)[lane8];
        const float4 ub = ((const float4*)s_ue)[8 + lane8];

        float accN = 0.0f, accI = 0.0f;

        auto compute_slot = [&](int k) {
            const float4* st4 = (const float4*)&s_buf[gw][k * 256];
            const float4 va = st4[grp * 16 + lane8];
            const float4 vb = st4[grp * 16 + 8 + lane8];
            float s = dot8(va, vb, ua, ub);
            s += __shfl_xor_sync(FULLMASK, s, 1);
            s += __shfl_xor_sync(FULLMASK, s, 2);
            s += __shfl_xor_sync(FULLMASK, s, 4);
            if (k < 8) {
                const float bi = __shfl_sync(FULLMASK, mybi, k * 4 + grp);
                if (lane8 == 0)
                    accN += fmaf(bu, bi, W3c) * softplusf(s);
            } else {
                const float c = __shfl_sync(FULLMASK, mysim, (k - 8) * 4 + grp);
                if (lane8 == 0)
                    accI += c * softplusf(-s);
            }
        };

        #define STEP(K, NLEFT) \
            cp_async_wait_n<NLEFT>(); __syncwarp(); compute_slot(K);
        STEP(0, 9) STEP(1, 8) STEP(2, 7) STEP(3, 6) STEP(4, 5)
        STEP(5, 4) STEP(6, 3) STEP(7, 2) STEP(8, 1) STEP(9, 0)
        #undef STEP

        accN = bfly(accN);
        accI = bfly(accI);
        if (lane == 0) { sN[gw] = accN; sI[gw] = accI; }

        // ---- matvec (warps 6-7: 64 threads, coalesced g_M rows) ----
        if (warp >= 6) {
            const int d = tid & 63;
            float acc = g_cpe[d];
            #pragma unroll 16
            for (int k = 0; k < ND; k++)
                acc = fmaf(s_ue[k], g_M[k * ND + d], acc);
            s_t[d] = acc;
        }

        // ---- positive score (warp 4) ----
        if (warp == 4) {
            const float4 pa = ((const float4*)s_pe)[lane8];
            const float4 pb = ((const float4*)s_pe)[8 + lane8];
            float s = dot8(pa, pb, ua, ub);
            s += __shfl_xor_sync(FULLMASK, s, 1);
            s += __shfl_xor_sync(FULLMASK, s, 2);
            s += __shfl_xor_sync(FULLMASK, s, 4);
            if (lane == 0) {
                const float bip = __ldg(a.beta_iD + p);
                sPosLoss = fmaf(bu, bip, W1c) * softplusf(-s);
            }
        }

        BAR_GATHER();   // s_t ready

        // ---- mse (warp 5) ----
        if (warp == 5) {
            float v = s_t[2*lane] * s_pe[2*lane] + s_t[2*lane+1] * s_pe[2*lane+1]
                    + g_cue[2*lane] * s_ue[2*lane] + g_cue[2*lane+1] * s_ue[2*lane+1];
            v = bfly(v);
            if (lane == 0) {
                const float pred = v + g_c0;
                const float dlt = pred - __ldg(a.rpkms + b);
                sMse = dlt * dlt;
            }
        }
    }

    __syncthreads();

    if (tid == 0) {
        float sn = sN[0] + sN[1] + sN[2] + sN[3];
        float si = sI[0] + sI[1] + sI[2] + sI[3];
        g_lossL[b] = sPosLoss + NEG_WEIGHTc * (sn * (1.0f / NNEG));
        g_lossI[b] = si;
        g_mseP[b]  = sMse;
        g_norm_partial[b] = sNorm[0] + sNorm[1] + sNorm[2] + sNorm[3];
    }

    // ---- last-block finalize ----
    __threadfence();
    if (tid == 0) sLast = (atomicAdd(&g_done, 1u) == (unsigned)(NB - 1));
    __syncthreads();
    if (!sLast) return;
    __threadfence();

    double aL = 0.0, aI = 0.0, aM = 0.0, aN = 0.0;
    for (int i = tid; i < NB; i += 256) {
        aL += (double)g_lossL[i];
        aI += (double)g_lossI[i];
        aM += (double)g_mseP[i];
        aN += (double)g_norm_partial[i];
    }
    __shared__ double rL[256], rI[256], rM[256], rN[256];
    rL[tid] = aL; rI[tid] = aI; rM[tid] = aM; rN[tid] = aN;
    __syncthreads();
    for (int o = 128; o; o >>= 1) {
        if (tid < o) {
            rL[tid] += rL[tid + o];
            rI[tid] += rI[tid + o];
            rM[tid] += rM[tid + o];
            rN[tid] += rN[tid + o];
        }
        __syncthreads();
    }
    if (tid == 0) {
        const double lossL = rL[0] / (double)NB;
        const double lossI = rI[0] * ((double)LAMBDAc / ((double)NB * (double)KNBR));
        const double mse   = rM[0] / (double)NB;
        const double norm  = rN[0] * 0.5 * (double)GAMMAc;
        float* out = a.out;
        out[0] = (float)(lossL + lossI + mse + norm);
        out[1] = (float)lossL;
        out[2] = (float)lossI;
        out[3] = 0.0f;
        out[4] = (float)mse;
        out[5] = (float)norm;
    }
}

// ---------------------------------------------------------------------------
// Launch
// ---------------------------------------------------------------------------
extern "C" void kernel_launch(void* const* d_in, const int* in_sizes, int n_in,
                              void* d_out, int out_size) {
    FusedArgs a;
    a.users     = (const int*)d_in[0];
    a.pos_items = (const int*)d_in[1];
    a.neg_items = (const int*)d_in[2];
    a.rpkms     = (const float*)d_in[3];
    a.user_emb  = (const float*)d_in[4];  a.nu = in_sizes[4];
    a.item_emb  = (const float*)d_in[5];  a.ni = in_sizes[5];
    a.beta_uD   = (const float*)d_in[6];
    a.beta_iD   = (const float*)d_in[7];
    a.ii_nbr    = (const int*)d_in[8];
    a.ii_con    = (const float*)d_in[9];
    const float* mse_u_w = (const float*)d_in[10];
    const float* mse_u_b = (const float*)d_in[11];
    const float* mse_i_w = (const float*)d_in[12];
    const float* mse_i_b = (const float*)d_in[13];
    a.sp[0] = mse_u_w;               a.sn[0] = in_sizes[10];
    a.sp[1] = mse_u_b;               a.sn[1] = in_sizes[11];
    a.sp[2] = mse_i_w;               a.sn[2] = in_sizes[12];
    a.sp[3] = mse_i_b;               a.sn[3] = in_sizes[13];
    a.sp[4] = (const float*)d_in[14]; a.sn[4] = in_sizes[14];
    a.sp[5] = (const float*)d_in[15]; a.sn[5] = in_sizes[15];
    a.sp[6] = (const float*)d_in[16]; a.sn[6] = in_sizes[16];
    a.sp[7] = (const float*)d_in[17]; a.sn[7] = in_sizes[17];
    a.out   = (float*)d_out;

    precompute_kernel<<<16, 256>>>(mse_u_w, mse_u_b, mse_i_w, mse_i_b);
    fused_kernel<<<NB, 256>>>(a);
}

// round 14
// speedup vs baseline: 1.1183x; 1.1183x over previous
#include <cuda_runtime.h>
#include <cstdint>
#include <math.h>

// ---------------------------------------------------------------------------
// Problem constants
// ---------------------------------------------------------------------------
#define NB      8192
#define ND      64
#define NNEG    128
#define KNBR    32

#define W1c     1e-6f
#define W3c     1e-6f
#define NEG_WEIGHTc 200.0f
#define GAMMAc  1e-4f
#define LAMBDAc 2.5f

#define FULLMASK 0xFFFFFFFFu

// ---------------------------------------------------------------------------
// Scratch (device globals)
// ---------------------------------------------------------------------------
__device__ float g_M[ND * ND];     // M = W_u^T W_i
__device__ float g_cpe[ND];        // W_i^T b_u
__device__ float g_cue[ND];        // W_u^T b_i
__device__ float g_c0;             // b_u . b_i
__device__ float g_norm_partial[NB];
__device__ float g_lossL[NB];
__device__ float g_lossI[NB];
__device__ float g_mseP[NB];
__device__ unsigned g_done;

__device__ __forceinline__ float softplusf(float x) {
    return fmaxf(x, 0.0f) + __logf(1.0f + __expf(-fabsf(x)));
}

__device__ __forceinline__ float bfly(float s) {
    #pragma unroll
    for (int o = 16; o; o >>= 1) s += __shfl_xor_sync(FULLMASK, s, o);
    return s;
}

__device__ __forceinline__ float dot8(float4 va, float4 vb, float4 ua, float4 ub) {
    float s = va.x * ua.x;
    s = fmaf(va.y, ua.y, s);
    s = fmaf(va.z, ua.z, s);
    s = fmaf(va.w, ua.w, s);
    s = fmaf(vb.x, ub.x, s);
    s = fmaf(vb.y, ub.y, s);
    s = fmaf(vb.z, ub.z, s);
    s = fmaf(vb.w, ub.w, s);
    return s;
}

#define BAR_GATHER() asm volatile("bar.sync 1, 128;" ::: "memory")

__device__ __forceinline__ void cp_async16(unsigned dst_smem, const void* src) {
    asm volatile("cp.async.ca.shared.global [%0], [%1], 16;"
                 :: "r"(dst_smem), "l"(src));
}
__device__ __forceinline__ void cp_async_commit() {
    asm volatile("cp.async.commit_group;" ::: "memory");
}
template <int N>
__device__ __forceinline__ void cp_async_wait_n() {
    asm volatile("cp.async.wait_group %0;" :: "n"(N) : "memory");
}

// ---------------------------------------------------------------------------
// Kernel 1: precompute M = W_u^T W_i (+ bias terms), smem-staged.
// Also resets the last-block counter for this graph replay.
// ---------------------------------------------------------------------------
__global__ void __launch_bounds__(256)
precompute_kernel(const float* __restrict__ wu, const float* __restrict__ bu,
                  const float* __restrict__ wi, const float* __restrict__ bi) {
    __shared__ float swu[ND * ND];
    __shared__ float swi[ND * ND];

    const int tid = threadIdx.x;
    if (blockIdx.x == 0 && tid == 0) g_done = 0u;

    {
        const float4* su = (const float4*)wu;
        const float4* si = (const float4*)wi;
        float4* du = (float4*)swu;
        float4* di = (float4*)swi;
        #pragma unroll
        for (int r = 0; r < 4; r++) {
            du[tid + r * 256] = su[tid + r * 256];
            di[tid + r * 256] = si[tid + r * 256];
        }
    }
    __syncthreads();

    const int idx = blockIdx.x * 256 + tid;
    const int a = idx >> 6;
    const int c = idx & 63;
    float a0 = 0.f, a1 = 0.f, a2 = 0.f, a3 = 0.f;
    #pragma unroll
    for (int d = 0; d < ND; d += 4) {
        a0 = fmaf(swu[(d + 0) * ND + a], swi[(d + 0) * ND + c], a0);
        a1 = fmaf(swu[(d + 1) * ND + a], swi[(d + 1) * ND + c], a1);
        a2 = fmaf(swu[(d + 2) * ND + a], swi[(d + 2) * ND + c], a2);
        a3 = fmaf(swu[(d + 3) * ND + a], swi[(d + 3) * ND + c], a3);
    }
    g_M[idx] = (a0 + a1) + (a2 + a3);

    if (blockIdx.x == 0 && tid < ND) {
        const int j = tid;
        float c1 = 0.0f, c2 = 0.0f;
        #pragma unroll 8
        for (int d = 0; d < ND; d++) {
            c1 = fmaf(swi[d * ND + j], bu[d], c1);
            c2 = fmaf(swu[d * ND + j], bi[d], c2);
        }
        g_cpe[j] = c1;
        g_cue[j] = c2;
        if (j == 0) {
            float s = 0.0f;
            #pragma unroll 8
            for (int d = 0; d < ND; d++) s = fmaf(bu[d], bi[d], s);
            g_c0 = s;
        }
    }
}

// ---------------------------------------------------------------------------
// Fused kernel args
// ---------------------------------------------------------------------------
struct FusedArgs {
    const int*   users;
    const int*   pos_items;
    const int*   neg_items;
    const float* rpkms;
    const float* user_emb;  long nu;
    const float* item_emb;  long ni;
    const float* beta_uD;
    const float* beta_iD;
    const int*   ii_nbr;
    const float* ii_con;
    const float* sp[8]; int sn[8];
    float* out;
};

// ---------------------------------------------------------------------------
// norm slice over 128 stream threads: __ldcs, 4 accumulators
// ---------------------------------------------------------------------------
__device__ __forceinline__ float norm_slice_128(const FusedArgs& a) {
    float acc0 = 0.0f, acc1 = 0.0f, acc2 = 0.0f, acc3 = 0.0f;
    const size_t tg = (size_t)blockIdx.x * 128 + threadIdx.x;
    const size_t stride = (size_t)gridDim.x * 128;

    const float4* pu = (const float4*)a.user_emb;
    const size_t mu = (size_t)a.nu >> 2;
    size_t i = tg;
    for (; i + 3 * stride < mu; i += 4 * stride) {
        float4 v0 = __ldcs(pu + i);
        float4 v1 = __ldcs(pu + i + stride);
        float4 v2 = __ldcs(pu + i + 2 * stride);
        float4 v3 = __ldcs(pu + i + 3 * stride);
        acc0 += v0.x*v0.x + v0.y*v0.y + v0.z*v0.z + v0.w*v0.w;
        acc1 += v1.x*v1.x + v1.y*v1.y + v1.z*v1.z + v1.w*v1.w;
        acc2 += v2.x*v2.x + v2.y*v2.y + v2.z*v2.z + v2.w*v2.w;
        acc3 += v3.x*v3.x + v3.y*v3.y + v3.z*v3.z + v3.w*v3.w;
    }
    for (; i < mu; i += stride) {
        float4 v = __ldcs(pu + i);
        acc0 += v.x*v.x + v.y*v.y + v.z*v.z + v.w*v.w;
    }
    const float4* pi = (const float4*)a.item_emb;
    const size_t mi = (size_t)a.ni >> 2;
    i = tg;
    for (; i + 3 * stride < mi; i += 4 * stride) {
        float4 v0 = __ldcs(pi + i);
        float4 v1 = __ldcs(pi + i + stride);
        float4 v2 = __ldcs(pi + i + 2 * stride);
        float4 v3 = __ldcs(pi + i + 3 * stride);
        acc0 += v0.x*v0.x + v0.y*v0.y + v0.z*v0.z + v0.w*v0.w;
        acc1 += v1.x*v1.x + v1.y*v1.y + v1.z*v1.z + v1.w*v1.w;
        acc2 += v2.x*v2.x + v2.y*v2.y + v2.z*v2.z + v2.w*v2.w;
        acc3 += v3.x*v3.x + v3.y*v3.y + v3.z*v3.z + v3.w*v3.w;
    }
    for (; i < mi; i += stride) {
        float4 v = __ldcs(pi + i);
        acc0 += v.x*v.x + v.y*v.y + v.z*v.z + v.w*v.w;
    }
    if (blockIdx.x == 0) {
        #pragma unroll
        for (int j = 0; j < 8; j++) {
            const float* q = a.sp[j];
            const int n = a.sn[j];
            for (int k = threadIdx.x; k < n; k += 128) {
                float v = q[k];
                acc0 += v * v;
            }
        }
    }
    return (acc0 + acc1) + (acc2 + acc3);
}

// ---------------------------------------------------------------------------
// Fused kernel: warp-specialized.
//  warps 0-3 : norm stream
//  warps 4-7 : cp.async 8-stage pipelined gathers + dots + matvec + pos + mse
// ---------------------------------------------------------------------------
__global__ void __launch_bounds__(256, 5)
fused_kernel(FusedArgs a) {
    const int b    = blockIdx.x;
    const int tid  = threadIdx.x;
    const int lane = tid & 31;
    const int warp = tid >> 5;

    // per gather warp: 8-stage ring of 4 rows (8 x 1KB)
    __shared__ __align__(16) float s_ring[4][8 * 4 * ND];
    __shared__ __align__(16) float s_ue[ND];
    __shared__ __align__(16) float s_pe[ND];
    __shared__ float s_t[ND];
    __shared__ float sN[4], sI[4];
    __shared__ float sPosLoss, sMse;
    __shared__ float sNorm[4];
    __shared__ bool  sLast;

    if (warp < 4) {
        // ================= STREAM WARPS =================
        float nacc = norm_slice_128(a);
        nacc = bfly(nacc);
        if (lane == 0) sNorm[warp] = nacc;
    } else {
        // ================= GATHER WARPS =================
        const int gw    = warp - 4;         // 0..3
        const int wg    = tid - 128;        // 0..127
        const int lane8 = lane & 7;
        const int grp   = lane >> 3;
        const int r16   = lane >> 4;        // 0/1: row pair for staging
        const int sub   = lane & 15;        // 16B chunk within row

        const int u = __ldg(a.users + b);
        const int p = __ldg(a.pos_items + b);

        if (wg < ND)      s_ue[wg]      = __ldg(a.user_emb + (size_t)u * ND + wg);
        else              s_pe[wg - ND] = __ldg(a.item_emb + (size_t)p * ND + (wg - ND));

        // index + scalar prefetch
        const int*   negb = a.neg_items + (size_t)b * NNEG + gw * 32;
        const int*   nbrp = a.ii_nbr   + (size_t)p * KNBR + gw * 8;
        const float* simp = a.ii_con   + (size_t)p * KNBR + gw * 8;
        const int   myneg = __ldg(negb + lane);
        const int   mynbr = (lane < 8) ? __ldg(nbrp + lane) : 0;
        const float mybi  = __ldg(a.beta_iD + myneg);
        const float mysim = (lane < 8) ? __ldg(simp + lane) : 0.0f;
        const float bu    = __ldg(a.beta_uD + u);

        const unsigned ring_base =
            (unsigned)__cvta_generic_to_shared(&s_ring[gw][0]);

        // issue stage for slot k (4 rows, 2 per staging thread), one group each
        auto issue_slot = [&](int k) {
            int j0, j1;
            if (k < 8) {
                j0 = __shfl_sync(FULLMASK, myneg, k * 4 + r16);
                j1 = __shfl_sync(FULLMASK, myneg, k * 4 + r16 + 2);
            } else {
                j0 = __shfl_sync(FULLMASK, mynbr, (k - 8) * 4 + r16);
                j1 = __shfl_sync(FULLMASK, mynbr, (k - 8) * 4 + r16 + 2);
            }
            const unsigned dst = ring_base + (unsigned)((k & 7) * 1024)
                               + (unsigned)(r16 * 256 + sub * 16);
            cp_async16(dst,       a.item_emb + (size_t)j0 * ND + sub * 4);
            cp_async16(dst + 512, a.item_emb + (size_t)j1 * ND + sub * 4);
            cp_async_commit();
        };

        // prologue: fill 7 stages (max pending = 7 groups)
        #pragma unroll
        for (int k = 0; k < 7; k++) issue_slot(k);

        BAR_GATHER();   // s_ue / s_pe ready among gather warps

        const float4 ua = ((const float4*)s_ue)[lane8];
        const float4 ub = ((const float4*)s_ue)[8 + lane8];

        float accN = 0.0f, accI = 0.0f;

        auto compute_slot = [&](int k) {
            const float4* st4 = (const float4*)&s_ring[gw][(k & 7) * 256];
            const float4 va = st4[grp * 16 + lane8];
            const float4 vb = st4[grp * 16 + 8 + lane8];
            float s = dot8(va, vb, ua, ub);
            s += __shfl_xor_sync(FULLMASK, s, 1);
            s += __shfl_xor_sync(FULLMASK, s, 2);
            s += __shfl_xor_sync(FULLMASK, s, 4);
            if (k < 8) {
                const float bi = __shfl_sync(FULLMASK, mybi, k * 4 + grp);
                if (lane8 == 0)
                    accN += fmaf(bu, bi, W3c) * softplusf(s);
            } else {
                const float c = __shfl_sync(FULLMASK, mysim, (k - 8) * 4 + grp);
                if (lane8 == 0)
                    accI += c * softplusf(-s);
            }
        };

        // steady state: slots 0..2 with issue-ahead of 7
        #pragma unroll
        for (int k = 0; k < 3; k++) {
            issue_slot(k + 7);
            cp_async_wait_n<7>();
            __syncwarp();
            compute_slot(k);
        }
        // tail: drain remaining 7 slots
        cp_async_wait_n<6>(); __syncwarp(); compute_slot(3);
        cp_async_wait_n<5>(); __syncwarp(); compute_slot(4);
        cp_async_wait_n<4>(); __syncwarp(); compute_slot(5);
        cp_async_wait_n<3>(); __syncwarp(); compute_slot(6);
        cp_async_wait_n<2>(); __syncwarp(); compute_slot(7);
        cp_async_wait_n<1>(); __syncwarp(); compute_slot(8);
        cp_async_wait_n<0>(); __syncwarp(); compute_slot(9);

        accN = bfly(accN);
        accI = bfly(accI);
        if (lane == 0) { sN[gw] = accN; sI[gw] = accI; }

        // ---- matvec (warps 6-7: 64 threads, coalesced g_M rows) ----
        if (warp >= 6) {
            const int d = tid & 63;
            float acc = g_cpe[d];
            #pragma unroll 16
            for (int k = 0; k < ND; k++)
                acc = fmaf(s_ue[k], g_M[k * ND + d], acc);
            s_t[d] = acc;
        }

        // ---- positive score (warp 4) ----
        if (warp == 4) {
            const float4 pa = ((const float4*)s_pe)[lane8];
            const float4 pb = ((const float4*)s_pe)[8 + lane8];
            float s = dot8(pa, pb, ua, ub);
            s += __shfl_xor_sync(FULLMASK, s, 1);
            s += __shfl_xor_sync(FULLMASK, s, 2);
            s += __shfl_xor_sync(FULLMASK, s, 4);
            if (lane == 0) {
                const float bip = __ldg(a.beta_iD + p);
                sPosLoss = fmaf(bu, bip, W1c) * softplusf(-s);
            }
        }

        BAR_GATHER();   // s_t ready

        // ---- mse (warp 5) ----
        if (warp == 5) {
            float v = s_t[2*lane] * s_pe[2*lane] + s_t[2*lane+1] * s_pe[2*lane+1]
                    + g_cue[2*lane] * s_ue[2*lane] + g_cue[2*lane+1] * s_ue[2*lane+1];
            v = bfly(v);
            if (lane == 0) {
                const float pred = v + g_c0;
                const float dlt = pred - __ldg(a.rpkms + b);
                sMse = dlt * dlt;
            }
        }
    }

    __syncthreads();

    if (tid == 0) {
        float sn = sN[0] + sN[1] + sN[2] + sN[3];
        float si = sI[0] + sI[1] + sI[2] + sI[3];
        g_lossL[b] = sPosLoss + NEG_WEIGHTc * (sn * (1.0f / NNEG));
        g_lossI[b] = si;
        g_mseP[b]  = sMse;
        g_norm_partial[b] = sNorm[0] + sNorm[1] + sNorm[2] + sNorm[3];
    }

    // ---- last-block finalize ----
    __threadfence();
    if (tid == 0) sLast = (atomicAdd(&g_done, 1u) == (unsigned)(NB - 1));
    __syncthreads();
    if (!sLast) return;
    __threadfence();

    double aL = 0.0, aI = 0.0, aM = 0.0, aN = 0.0;
    for (int i = tid; i < NB; i += 256) {
        aL += (double)g_lossL[i];
        aI += (double)g_lossI[i];
        aM += (double)g_mseP[i];
        aN += (double)g_norm_partial[i];
    }
    __shared__ double rL[256], rI[256], rM[256], rN[256];
    rL[tid] = aL; rI[tid] = aI; rM[tid] = aM; rN[tid] = aN;
    __syncthreads();
    for (int o = 128; o; o >>= 1) {
        if (tid < o) {
            rL[tid] += rL[tid + o];
            rI[tid] += rI[tid + o];
            rM[tid] += rM[tid + o];
            rN[tid] += rN[tid + o];
        }
        __syncthreads();
    }
    if (tid == 0) {
        const double lossL = rL[0] / (double)NB;
        const double lossI = rI[0] * ((double)LAMBDAc / ((double)NB * (double)KNBR));
        const double mse   = rM[0] / (double)NB;
        const double norm  = rN[0] * 0.5 * (double)GAMMAc;
        float* out = a.out;
        out[0] = (float)(lossL + lossI + mse + norm);
        out[1] = (float)lossL;
        out[2] = (float)lossI;
        out[3] = 0.0f;
        out[4] = (float)mse;
        out[5] = (float)norm;
    }
}

// ---------------------------------------------------------------------------
// Launch
// ---------------------------------------------------------------------------
extern "C" void kernel_launch(void* const* d_in, const int* in_sizes, int n_in,
                              void* d_out, int out_size) {
    FusedArgs a;
    a.users     = (const int*)d_in[0];
    a.pos_items = (const int*)d_in[1];
    a.neg_items = (const int*)d_in[2];
    a.rpkms     = (const float*)d_in[3];
    a.user_emb  = (const float*)d_in[4];  a.nu = in_sizes[4];
    a.item_emb  = (const float*)d_in[5];  a.ni = in_sizes[5];
    a.beta_uD   = (const float*)d_in[6];
    a.beta_iD   = (const float*)d_in[7];
    a.ii_nbr    = (const int*)d_in[8];
    a.ii_con    = (const float*)d_in[9];
    const float* mse_u_w = (const float*)d_in[10];
    const float* mse_u_b = (const float*)d_in[11];
    const float* mse_i_w = (const float*)d_in[12];
    const float* mse_i_b = (const float*)d_in[13];
    a.sp[0] = mse_u_w;               a.sn[0] = in_sizes[10];
    a.sp[1] = mse_u_b;               a.sn[1] = in_sizes[11];
    a.sp[2] = mse_i_w;               a.sn[2] = in_sizes[12];
    a.sp[3] = mse_i_b;               a.sn[3] = in_sizes[13];
    a.sp[4] = (const float*)d_in[14]; a.sn[4] = in_sizes[14];
    a.sp[5] = (const float*)d_in[15]; a.sn[5] = in_sizes[15];
    a.sp[6] = (const float*)d_in[16]; a.sn[6] = in_sizes[16];
    a.sp[7] = (const float*)d_in[17]; a.sn[7] = in_sizes[17];
    a.out   = (float*)d_out;

    precompute_kernel<<<16, 256>>>(mse_u_w, mse_u_b, mse_i_w, mse_i_b);
    fused_kernel<<<NB, 256>>>(a);
}

// round 15
// speedup vs baseline: 1.7339x; 1.5505x over previous
#include <cuda_runtime.h>
#include <cstdint>
#include <math.h>

// ---------------------------------------------------------------------------
// Problem constants
// ---------------------------------------------------------------------------
#define NB      8192
#define ND      64
#define NNEG    128
#define KNBR    32

#define W1c     1e-6f
#define W3c     1e-6f
#define NEG_WEIGHTc 200.0f
#define GAMMAc  1e-4f
#define LAMBDAc 2.5f

#define FULLMASK 0xFFFFFFFFu

// ---------------------------------------------------------------------------
// Scratch (device globals)
// ---------------------------------------------------------------------------
__device__ float g_M[ND * ND];     // M = W_u^T W_i
__device__ float g_cpe[ND];        // W_i^T b_u
__device__ float g_cue[ND];        // W_u^T b_i
__device__ float g_c0;             // b_u . b_i
__device__ float g_norm_partial[NB];
__device__ float g_lossL[NB];
__device__ float g_lossI[NB];
__device__ float g_mseP[NB];

__device__ __forceinline__ float softplusf(float x) {
    return fmaxf(x, 0.0f) + __logf(1.0f + __expf(-fabsf(x)));
}

__device__ __forceinline__ float bfly(float s) {
    #pragma unroll
    for (int o = 16; o; o >>= 1) s += __shfl_xor_sync(FULLMASK, s, o);
    return s;
}

__device__ __forceinline__ float dot8(float4 va, float4 vb, float4 ua, float4 ub) {
    float s = va.x * ua.x;
    s = fmaf(va.y, ua.y, s);
    s = fmaf(va.z, ua.z, s);
    s = fmaf(va.w, ua.w, s);
    s = fmaf(vb.x, ub.x, s);
    s = fmaf(vb.y, ub.y, s);
    s = fmaf(vb.z, ub.z, s);
    s = fmaf(vb.w, ub.w, s);
    return s;
}

#define BAR_GATHER() asm volatile("bar.sync 1, 128;" ::: "memory")

__device__ __forceinline__ void cp_async16(unsigned dst_smem, const void* src) {
    asm volatile("cp.async.ca.shared.global [%0], [%1], 16;"
                 :: "r"(dst_smem), "l"(src));
}
__device__ __forceinline__ void cp_async_commit() {
    asm volatile("cp.async.commit_group;" ::: "memory");
}
template <int N>
__device__ __forceinline__ void cp_async_wait_n() {
    asm volatile("cp.async.wait_group %0;" :: "n"(N) : "memory");
}

// ---------------------------------------------------------------------------
// Kernel 1: precompute M = W_u^T W_i (+ bias terms), smem-staged.
// ---------------------------------------------------------------------------
__global__ void __launch_bounds__(256)
precompute_kernel(const float* __restrict__ wu, const float* __restrict__ bu,
                  const float* __restrict__ wi, const float* __restrict__ bi) {
    __shared__ float swu[ND * ND];
    __shared__ float swi[ND * ND];

    const int tid = threadIdx.x;

    {
        const float4* su = (const float4*)wu;
        const float4* si = (const float4*)wi;
        float4* du = (float4*)swu;
        float4* di = (float4*)swi;
        #pragma unroll
        for (int r = 0; r < 4; r++) {
            du[tid + r * 256] = su[tid + r * 256];
            di[tid + r * 256] = si[tid + r * 256];
        }
    }
    __syncthreads();

    const int idx = blockIdx.x * 256 + tid;
    const int a = idx >> 6;
    const int c = idx & 63;
    float a0 = 0.f, a1 = 0.f, a2 = 0.f, a3 = 0.f;
    #pragma unroll
    for (int d = 0; d < ND; d += 4) {
        a0 = fmaf(swu[(d + 0) * ND + a], swi[(d + 0) * ND + c], a0);
        a1 = fmaf(swu[(d + 1) * ND + a], swi[(d + 1) * ND + c], a1);
        a2 = fmaf(swu[(d + 2) * ND + a], swi[(d + 2) * ND + c], a2);
        a3 = fmaf(swu[(d + 3) * ND + a], swi[(d + 3) * ND + c], a3);
    }
    g_M[idx] = (a0 + a1) + (a2 + a3);

    if (blockIdx.x == 0 && tid < ND) {
        const int j = tid;
        float c1 = 0.0f, c2 = 0.0f;
        #pragma unroll 8
        for (int d = 0; d < ND; d++) {
            c1 = fmaf(swi[d * ND + j], bu[d], c1);
            c2 = fmaf(swu[d * ND + j], bi[d], c2);
        }
        g_cpe[j] = c1;
        g_cue[j] = c2;
        if (j == 0) {
            float s = 0.0f;
            #pragma unroll 8
            for (int d = 0; d < ND; d++) s = fmaf(bu[d], bi[d], s);
            g_c0 = s;
        }
    }
}

// ---------------------------------------------------------------------------
// Fused kernel args
// ---------------------------------------------------------------------------
struct FusedArgs {
    const int*   users;
    const int*   pos_items;
    const int*   neg_items;
    const float* rpkms;
    const float* user_emb;  long nu;
    const float* item_emb;  long ni;
    const float* beta_uD;
    const float* beta_iD;
    const int*   ii_nbr;
    const float* ii_con;
    const float* sp[8]; int sn[8];
    float* out;
};

// ---------------------------------------------------------------------------
// norm slice over 128 stream threads: __ldcs, 4 accumulators
// ---------------------------------------------------------------------------
__device__ __forceinline__ float norm_slice_128(const FusedArgs& a) {
    float acc0 = 0.0f, acc1 = 0.0f, acc2 = 0.0f, acc3 = 0.0f;
    const size_t tg = (size_t)blockIdx.x * 128 + threadIdx.x;
    const size_t stride = (size_t)gridDim.x * 128;

    const float4* pu = (const float4*)a.user_emb;
    const size_t mu = (size_t)a.nu >> 2;
    size_t i = tg;
    for (; i + 3 * stride < mu; i += 4 * stride) {
        float4 v0 = __ldcs(pu + i);
        float4 v1 = __ldcs(pu + i + stride);
        float4 v2 = __ldcs(pu + i + 2 * stride);
        float4 v3 = __ldcs(pu + i + 3 * stride);
        acc0 += v0.x*v0.x + v0.y*v0.y + v0.z*v0.z + v0.w*v0.w;
        acc1 += v1.x*v1.x + v1.y*v1.y + v1.z*v1.z + v1.w*v1.w;
        acc2 += v2.x*v2.x + v2.y*v2.y + v2.z*v2.z + v2.w*v2.w;
        acc3 += v3.x*v3.x + v3.y*v3.y + v3.z*v3.z + v3.w*v3.w;
    }
    for (; i < mu; i += stride) {
        float4 v = __ldcs(pu + i);
        acc0 += v.x*v.x + v.y*v.y + v.z*v.z + v.w*v.w;
    }
    const float4* pi = (const float4*)a.item_emb;
    const size_t mi = (size_t)a.ni >> 2;
    i = tg;
    for (; i + 3 * stride < mi; i += 4 * stride) {
        float4 v0 = __ldcs(pi + i);
        float4 v1 = __ldcs(pi + i + stride);
        float4 v2 = __ldcs(pi + i + 2 * stride);
        float4 v3 = __ldcs(pi + i + 3 * stride);
        acc0 += v0.x*v0.x + v0.y*v0.y + v0.z*v0.z + v0.w*v0.w;
        acc1 += v1.x*v1.x + v1.y*v1.y + v1.z*v1.z + v1.w*v1.w;
        acc2 += v2.x*v2.x + v2.y*v2.y + v2.z*v2.z + v2.w*v2.w;
        acc3 += v3.x*v3.x + v3.y*v3.y + v3.z*v3.z + v3.w*v3.w;
    }
    for (; i < mi; i += stride) {
        float4 v = __ldcs(pi + i);
        acc0 += v.x*v.x + v.y*v.y + v.z*v.z + v.w*v.w;
    }
    if (blockIdx.x == 0) {
        #pragma unroll
        for (int j = 0; j < 8; j++) {
            const float* q = a.sp[j];
            const int n = a.sn[j];
            for (int k = threadIdx.x; k < n; k += 128) {
                float v = q[k];
                acc0 += v * v;
            }
        }
    }
    return (acc0 + acc1) + (acc2 + acc3);
}

// ---------------------------------------------------------------------------
// Fused kernel: warp-specialized.
//  warps 0-3 : norm stream
//  warps 4-7 : cp.async 4-stage pipelined gathers + dots + matvec + pos + mse
// ---------------------------------------------------------------------------
__global__ void __launch_bounds__(256, 5)
fused_kernel(FusedArgs a) {
    const int b    = blockIdx.x;
    const int tid  = threadIdx.x;
    const int lane = tid & 31;
    const int warp = tid >> 5;

    // per gather warp: 4-stage ring of 4 rows (4 x 1KB)
    __shared__ __align__(16) float s_ring[4][4 * 4 * ND];
    __shared__ __align__(16) float s_ue[ND];
    __shared__ __align__(16) float s_pe[ND];
    __shared__ float s_t[ND];
    __shared__ float sN[4], sI[4];
    __shared__ float sPosLoss, sMse;
    __shared__ float sNorm[4];

    if (warp < 4) {
        // ================= STREAM WARPS =================
        float nacc = norm_slice_128(a);
        nacc = bfly(nacc);
        if (lane == 0) sNorm[warp] = nacc;
    } else {
        // ================= GATHER WARPS =================
        const int gw    = warp - 4;         // 0..3
        const int wg    = tid - 128;        // 0..127
        const int lane8 = lane & 7;
        const int grp   = lane >> 3;
        const int r16   = lane >> 4;        // 0/1: row pair for staging
        const int sub   = lane & 15;        // 16B chunk within row

        const int u = __ldg(a.users + b);
        const int p = __ldg(a.pos_items + b);

        if (wg < ND)      s_ue[wg]      = __ldg(a.user_emb + (size_t)u * ND + wg);
        else              s_pe[wg - ND] = __ldg(a.item_emb + (size_t)p * ND + (wg - ND));

        // index + scalar prefetch
        const int*   negb = a.neg_items + (size_t)b * NNEG + gw * 32;
        const int*   nbrp = a.ii_nbr   + (size_t)p * KNBR + gw * 8;
        const float* simp = a.ii_con   + (size_t)p * KNBR + gw * 8;
        const int   myneg = __ldg(negb + lane);
        const int   mynbr = (lane < 8) ? __ldg(nbrp + lane) : 0;
        const float mybi  = __ldg(a.beta_iD + myneg);
        const float mysim = (lane < 8) ? __ldg(simp + lane) : 0.0f;
        const float bu    = __ldg(a.beta_uD + u);

        const unsigned ring_base =
            (unsigned)__cvta_generic_to_shared(&s_ring[gw][0]);

        // issue stage for slot k (4 rows, 2 per staging thread)
        auto issue_slot = [&](int k) {
            int j0, j1;
            if (k < 8) {
                j0 = __shfl_sync(FULLMASK, myneg, k * 4 + r16);
                j1 = __shfl_sync(FULLMASK, myneg, k * 4 + r16 + 2);
            } else {
                j0 = __shfl_sync(FULLMASK, mynbr, (k - 8) * 4 + r16);
                j1 = __shfl_sync(FULLMASK, mynbr, (k - 8) * 4 + r16 + 2);
            }
            const unsigned dst = ring_base + (unsigned)((k & 3) * 1024)
                               + (unsigned)(r16 * 256 + sub * 16);
            cp_async16(dst,       a.item_emb + (size_t)j0 * ND + sub * 4);
            cp_async16(dst + 512, a.item_emb + (size_t)j1 * ND + sub * 4);
            cp_async_commit();
        };

        // prologue: fill 3 stages (only depends on myneg)
        issue_slot(0);
        issue_slot(1);
        issue_slot(2);

        BAR_GATHER();   // s_ue / s_pe ready among gather warps

        const float4 ua = ((const float4*)s_ue)[lane8];
        const float4 ub = ((const float4*)s_ue)[8 + lane8];

        float accN = 0.0f, accI = 0.0f;

        auto compute_slot = [&](int k) {
            const float4* st4 = (const float4*)&s_ring[gw][(k & 3) * 256];
            const float4 va = st4[grp * 16 + lane8];
            const float4 vb = st4[grp * 16 + 8 + lane8];
            float s = dot8(va, vb, ua, ub);
            s += __shfl_xor_sync(FULLMASK, s, 1);
            s += __shfl_xor_sync(FULLMASK, s, 2);
            s += __shfl_xor_sync(FULLMASK, s, 4);
            if (k < 8) {
                const float bi = __shfl_sync(FULLMASK, mybi, k * 4 + grp);
                if (lane8 == 0)
                    accN += fmaf(bu, bi, W3c) * softplusf(s);
            } else {
                const float c = __shfl_sync(FULLMASK, mysim, (k - 8) * 4 + grp);
                if (lane8 == 0)
                    accI += c * softplusf(-s);
            }
        };

        // steady state: slots 0..6 with issue-ahead
        #pragma unroll
        for (int k = 0; k < 7; k++) {
            issue_slot(k + 3);
            cp_async_wait_n<3>();
            __syncwarp();
            compute_slot(k);
        }
        // tail
        cp_async_wait_n<2>(); __syncwarp(); compute_slot(7);
        cp_async_wait_n<1>(); __syncwarp(); compute_slot(8);
        cp_async_wait_n<0>(); __syncwarp(); compute_slot(9);

        accN = bfly(accN);
        accI = bfly(accI);
        if (lane == 0) { sN[gw] = accN; sI[gw] = accI; }

        // ---- matvec (warps 6-7: 64 threads, coalesced g_M rows) ----
        if (warp >= 6) {
            const int d = tid & 63;
            float acc = g_cpe[d];
            #pragma unroll 16
            for (int k = 0; k < ND; k++)
                acc = fmaf(s_ue[k], g_M[k * ND + d], acc);
            s_t[d] = acc;
        }

        // ---- positive score (warp 4) ----
        if (warp == 4) {
            const float4 pa = ((const float4*)s_pe)[lane8];
            const float4 pb = ((const float4*)s_pe)[8 + lane8];
            float s = dot8(pa, pb, ua, ub);
            s += __shfl_xor_sync(FULLMASK, s, 1);
            s += __shfl_xor_sync(FULLMASK, s, 2);
            s += __shfl_xor_sync(FULLMASK, s, 4);
            if (lane == 0) {
                const float bip = __ldg(a.beta_iD + p);
                sPosLoss = fmaf(bu, bip, W1c) * softplusf(-s);
            }
        }

        BAR_GATHER();   // s_t ready

        // ---- mse (warp 5) ----
        if (warp == 5) {
            float v = s_t[2*lane] * s_pe[2*lane] + s_t[2*lane+1] * s_pe[2*lane+1]
                    + g_cue[2*lane] * s_ue[2*lane] + g_cue[2*lane+1] * s_ue[2*lane+1];
            v = bfly(v);
            if (lane == 0) {
                const float pred = v + g_c0;
                const float dlt = pred - __ldg(a.rpkms + b);
                sMse = dlt * dlt;
            }
        }
    }

    __syncthreads();

    if (tid == 0) {
        float sn = sN[0] + sN[1] + sN[2] + sN[3];
        float si = sI[0] + sI[1] + sI[2] + sI[3];
        g_lossL[b] = sPosLoss + NEG_WEIGHTc * (sn * (1.0f / NNEG));
        g_lossI[b] = si;
        g_mseP[b]  = sMse;
        g_norm_partial[b] = sNorm[0] + sNorm[1] + sNorm[2] + sNorm[3];
    }
}

// ---------------------------------------------------------------------------
// Kernel 3: deterministic final reduction -> 6 outputs (no global atomics)
// ---------------------------------------------------------------------------
__global__ void __launch_bounds__(256)
finalize_kernel(float* __restrict__ out) {
    const int tid = threadIdx.x;
    double aL = 0.0, aI = 0.0, aM = 0.0, aN = 0.0;
    for (int i = tid; i < NB; i += 256) {
        aL += (double)g_lossL[i];
        aI += (double)g_lossI[i];
        aM += (double)g_mseP[i];
        aN += (double)g_norm_partial[i];
    }
    __shared__ double rL[256], rI[256], rM[256], rN[256];
    rL[tid] = aL; rI[tid] = aI; rM[tid] = aM; rN[tid] = aN;
    __syncthreads();
    for (int o = 128; o; o >>= 1) {
        if (tid < o) {
            rL[tid] += rL[tid + o];
            rI[tid] += rI[tid + o];
            rM[tid] += rM[tid + o];
            rN[tid] += rN[tid + o];
        }
        __syncthreads();
    }
    if (tid == 0) {
        const double lossL = rL[0] / (double)NB;
        const double lossI = rI[0] * ((double)LAMBDAc / ((double)NB * (double)KNBR));
        const double mse   = rM[0] / (double)NB;
        const double norm  = rN[0] * 0.5 * (double)GAMMAc;
        out[0] = (float)(lossL + lossI + mse + norm);
        out[1] = (float)lossL;
        out[2] = (float)lossI;
        out[3] = 0.0f;
        out[4] = (float)mse;
        out[5] = (float)norm;
    }
}

// ---------------------------------------------------------------------------
// Launch
// ---------------------------------------------------------------------------
extern "C" void kernel_launch(void* const* d_in, const int* in_sizes, int n_in,
                              void* d_out, int out_size) {
    FusedArgs a;
    a.users     = (const int*)d_in[0];
    a.pos_items = (const int*)d_in[1];
    a.neg_items = (const int*)d_in[2];
    a.rpkms     = (const float*)d_in[3];
    a.user_emb  = (const float*)d_in[4];  a.nu = in_sizes[4];
    a.item_emb  = (const float*)d_in[5];  a.ni = in_sizes[5];
    a.beta_uD   = (const float*)d_in[6];
    a.beta_iD   = (const float*)d_in[7];
    a.ii_nbr    = (const int*)d_in[8];
    a.ii_con    = (const float*)d_in[9];
    const float* mse_u_w = (const float*)d_in[10];
    const float* mse_u_b = (const float*)d_in[11];
    const float* mse_i_w = (const float*)d_in[12];
    const float* mse_i_b = (const float*)d_in[13];
    a.sp[0] = mse_u_w;               a.sn[0] = in_sizes[10];
    a.sp[1] = mse_u_b;               a.sn[1] = in_sizes[11];
    a.sp[2] = mse_i_w;               a.sn[2] = in_sizes[12];
    a.sp[3] = mse_i_b;               a.sn[3] = in_sizes[13];
    a.sp[4] = (const float*)d_in[14]; a.sn[4] = in_sizes[14];
    a.sp[5] = (const float*)d_in[15]; a.sn[5] = in_sizes[15];
    a.sp[6] = (const float*)d_in[16]; a.sn[6] = in_sizes[16];
    a.sp[7] = (const float*)d_in[17]; a.sn[7] = in_sizes[17];
    a.out   = (float*)d_out;

    precompute_kernel<<<16, 256>>>(mse_u_w, mse_u_b, mse_i_w, mse_i_b);
    fused_kernel<<<NB, 256>>>(a);
    finalize_kernel<<<1, 256>>>((float*)d_out);
}